// round 4
// baseline (speedup 1.0000x reference)
#include <cuda_runtime.h>
#include <cuda_bf16.h>
#include <cstdint>

// VoxelPooler: single-pass binning into fixed-capacity row segments, then
// per-row shared-memory pooling with race-free (non-atomic) accumulation.
//
// geometry [B,N,D,H,W,3] f32, features [B,N,D,H,W,64] f32
// output   [B, Z*C, X, Y] f32, Z=8 C=64 X=200 Y=200
//
// Rows = (b,z,x): 6400. Mean ~72 valid points/row (Poisson), CAP=512 gives
// astronomically safe headroom. In rowpool, warp w owns y%8==w and lane l owns
// channels {l, l+32}: every (c,y) smem cell has a unique owner thread, so
// accumulation is plain LDS+FADD+STS (rt ~2cyc) instead of ATOMS (64cyc/warp).

constexpr int GX = 200;
constexpr int GY = 200;
constexpr int GZ = 8;
constexpr int CH = 64;
constexpr int XY = GX * GY;
constexpr int NB = 4;
constexpr int PPB   = 6 * 41 * 16 * 44;    // 173184
constexpr int PTOT  = NB * PPB;            // 692736
constexpr int NROWS = NB * GZ * GX;        // 6400
constexpr int PADY  = GY + 1;              // 201: bank stride 9, coprime 32
constexpr int CAP   = 512;                 // slots per row segment

__device__ int      d_count[NROWS];
__device__ unsigned d_plist[(size_t)NROWS * CAP];   // (p<<8)|y  (13.1 MB)

__global__ void vp_zero_count() {
    int i = blockIdx.x * blockDim.x + threadIdx.x;
    if (i < NROWS) d_count[i] = 0;
}

__global__ void __launch_bounds__(256) vp_bin_fill(
    const float* __restrict__ geo,
    const float* __restrict__ vsize,
    const float* __restrict__ vorig)
{
    int p = blockIdx.x * blockDim.x + threadIdx.x;
    if (p >= PTOT) return;

    const float* g = geo + (size_t)p * 3;
    float px = g[0], py = g[1], pz = g[2];

    // fp32 semantics matching jnp exactly: sub(rn), div(rn), floorf, int cast
    int ix = (int)floorf(__fdiv_rn(px - __ldg(&vorig[0]), __ldg(&vsize[0])));
    int iy = (int)floorf(__fdiv_rn(py - __ldg(&vorig[1]), __ldg(&vsize[1])));
    int iz = (int)floorf(__fdiv_rn(pz - __ldg(&vorig[2]), __ldg(&vsize[2])));

    if ((unsigned)ix >= (unsigned)GX ||
        (unsigned)iy >= (unsigned)GY ||
        (unsigned)iz >= (unsigned)GZ) return;     // ref scatters zeros: no-op

    int b = p / PPB;
    int row = (b * GZ + iz) * GX + ix;
    int pos = atomicAdd(&d_count[row], 1);
    if (pos < CAP)
        d_plist[(size_t)row * CAP + pos] = ((unsigned)p << 8) | (unsigned)iy;
}

// One CTA per (b,z,x) row.
__global__ void __launch_bounds__(256) vp_rowpool(
    const float* __restrict__ feat,
    float* __restrict__ out)
{
    __shared__ float    acc[CH * PADY];   // 51456 B
    __shared__ unsigned ent[CAP];         //  2048 B

    int r = blockIdx.x;
    int tid = threadIdx.x;
    int warp = tid >> 5, lane = tid & 31;

    // zero the tile (float4)
    float4* accv = reinterpret_cast<float4*>(acc);
    for (int i = tid; i < (CH * PADY) / 4; i += 256)
        accv[i] = make_float4(0.f, 0.f, 0.f, 0.f);

    int n = d_count[r];
    if (n > CAP) n = CAP;
    for (int i = tid; i < n; i += 256)
        ent[i] = d_plist[(size_t)r * CAP + i];
    __syncthreads();

    // warp w owns y%8==w; lane l owns channels l and l+32 -> no races.
    for (int i = 0; i < n; ++i) {
        unsigned e = ent[i];                  // broadcast LDS, warp-uniform
        int y = (int)(e & 255u);
        if ((y & 7) != warp) continue;        // warp-uniform branch
        const float* f = feat + (size_t)(e >> 8) * CH;
        float f0 = f[lane];
        float f1 = f[lane + 32];
        acc[lane * PADY + y]        += f0;    // banks (9l+y)%32: conflict-free
        acc[(lane + 32) * PADY + y] += f1;
    }
    __syncthreads();

    // stream tile to gmem: 64ch x 50 float4, coalesced
    int b  = r / (GZ * GX);
    int zx = r % (GZ * GX);
    int z = zx / GX, x = zx % GX;
    float* ob = out + ((size_t)(b * GZ + z) * CH) * XY + (size_t)x * GY;

    for (int i = tid; i < CH * (GY / 4); i += 256) {
        int c  = i / (GY / 4);
        int y4 = (i % (GY / 4)) * 4;
        const float* a = &acc[c * PADY + y4];
        float4 v = make_float4(a[0], a[1], a[2], a[3]);
        *reinterpret_cast<float4*>(ob + (size_t)c * XY + y4) = v;
    }
}

extern "C" void kernel_launch(void* const* d_in, const int* in_sizes, int n_in,
                              void* d_out, int out_size)
{
    const float* geo   = (const float*)d_in[0];
    const float* feat  = (const float*)d_in[1];
    const float* vsize = (const float*)d_in[2];
    const float* vorig = (const float*)d_in[3];
    float* out = (float*)d_out;

    vp_zero_count<<<(NROWS + 255) / 256, 256>>>();
    vp_bin_fill<<<(PTOT + 255) / 256, 256>>>(geo, vsize, vorig);
    vp_rowpool<<<NROWS, 256>>>(feat, out);
}

// round 5
// speedup vs baseline: 1.6344x; 1.6344x over previous
#include <cuda_runtime.h>
#include <cuda_bf16.h>
#include <cstdint>

// VoxelPooler: single-pass binning into fixed-capacity row segments, then
// per-row smem pooling. Entries are counting-sorted by y%8 inside smem so
// warp w processes ONLY its own y-class segment (entry-parallel across warps,
// race-free within: lane l owns channels {l, l+32}).
//
// geometry [B,N,D,H,W,3] f32, features [B,N,D,H,W,64] f32
// output   [B, Z*C, X, Y] f32, Z=8 C=64 X=200 Y=200

constexpr int GX = 200;
constexpr int GY = 200;
constexpr int GZ = 8;
constexpr int CH = 64;
constexpr int XY = GX * GY;
constexpr int NB = 4;
constexpr int PPB   = 6 * 41 * 16 * 44;    // 173184
constexpr int PTOT  = NB * PPB;            // 692736
constexpr int NROWS = NB * GZ * GX;        // 6400
constexpr int PADY  = GY + 1;              // 201: bank stride 9, coprime 32
constexpr int CAP   = 512;                 // slots per row (mean occupancy ~72)

__device__ int      d_count[NROWS];                 // zero-init; re-zeroed by rowpool
__device__ unsigned d_plist[(size_t)NROWS * CAP];   // (p<<8)|y  (13.1 MB)

__global__ void __launch_bounds__(256) vp_bin_fill(
    const float* __restrict__ geo,
    const float* __restrict__ vsize,
    const float* __restrict__ vorig)
{
    int p = blockIdx.x * blockDim.x + threadIdx.x;
    if (p >= PTOT) return;

    const float* g = geo + (size_t)p * 3;
    float px = g[0], py = g[1], pz = g[2];

    // fp32 semantics matching jnp exactly: sub(rn), div(rn), floorf, int cast
    int ix = (int)floorf(__fdiv_rn(px - __ldg(&vorig[0]), __ldg(&vsize[0])));
    int iy = (int)floorf(__fdiv_rn(py - __ldg(&vorig[1]), __ldg(&vsize[1])));
    int iz = (int)floorf(__fdiv_rn(pz - __ldg(&vorig[2]), __ldg(&vsize[2])));

    if ((unsigned)ix >= (unsigned)GX ||
        (unsigned)iy >= (unsigned)GY ||
        (unsigned)iz >= (unsigned)GZ) return;     // ref scatters zeros: no-op

    int b = p / PPB;
    int row = (b * GZ + iz) * GX + ix;
    int pos = atomicAdd(&d_count[row], 1);
    if (pos < CAP)
        d_plist[(size_t)row * CAP + pos] = ((unsigned)p << 8) | (unsigned)iy;
}

// One CTA per (b,z,x) row.
__global__ void __launch_bounds__(256) vp_rowpool(
    const float* __restrict__ feat,
    float* __restrict__ out)
{
    __shared__ float    acc[CH * PADY];   // 51456 B
    __shared__ unsigned sorted[CAP];      //  2048 B
    __shared__ int      cls[8];           // class counts / cursors
    __shared__ int      off[9];           // class offsets

    int r = blockIdx.x;
    int tid = threadIdx.x;
    int warp = tid >> 5, lane = tid & 31;

    // zero the tile (float4) + class counters
    float4* accv = reinterpret_cast<float4*>(acc);
    for (int i = tid; i < (CH * PADY) / 4; i += 256)
        accv[i] = make_float4(0.f, 0.f, 0.f, 0.f);
    if (tid < 8) cls[tid] = 0;

    int n = d_count[r];                   // broadcast load (same address)
    if (n > CAP) n = CAP;
    const unsigned* seg = d_plist + (size_t)r * CAP;

    // phase A: read entries into regs, count classes
    unsigned e0 = 0, e1 = 0;
    bool h0 = tid < n, h1 = tid + 256 < n;
    if (h0) e0 = seg[tid];
    if (h1) e1 = seg[tid + 256];
    __syncthreads();                      // acc zero + cls zero complete
    if (h0) atomicAdd(&cls[e0 & 7], 1);
    if (h1) atomicAdd(&cls[e1 & 7], 1);
    __syncthreads();

    // phase B: 8-wide exclusive prefix; reset row counter for the next launch
    if (tid == 0) {
        int run = 0;
        #pragma unroll
        for (int k = 0; k < 8; ++k) { off[k] = run; run += cls[k]; cls[k] = run - cls[k]; }
        off[8] = run;
        d_count[r] = 0;
    }
    __syncthreads();

    // phase C: place entries into class segments
    if (h0) sorted[atomicAdd(&cls[e0 & 7], 1)] = e0;
    if (h1) sorted[atomicAdd(&cls[e1 & 7], 1)] = e1;
    __syncthreads();

    // phase D: warp w consumes class w; lane l owns channels {l, l+32}.
    int i  = off[warp];
    int s1 = off[warp + 1];
    for (; i + 1 < s1; i += 2) {          // unroll-2: two loads in flight
        unsigned a = sorted[i], b = sorted[i + 1];
        const float* fa = feat + (size_t)(a >> 8) * CH;
        const float* fb = feat + (size_t)(b >> 8) * CH;
        float a0 = fa[lane], a1 = fa[lane + 32];
        float b0 = fb[lane], b1 = fb[lane + 32];
        int ya = (int)(a & 255u), yb = (int)(b & 255u);
        acc[lane * PADY + ya]        += a0;   // banks (9l+y)%32: conflict-free
        acc[(lane + 32) * PADY + ya] += a1;
        acc[lane * PADY + yb]        += b0;
        acc[(lane + 32) * PADY + yb] += b1;
    }
    if (i < s1) {
        unsigned a = sorted[i];
        const float* fa = feat + (size_t)(a >> 8) * CH;
        float a0 = fa[lane], a1 = fa[lane + 32];
        int ya = (int)(a & 255u);
        acc[lane * PADY + ya]        += a0;
        acc[(lane + 32) * PADY + ya] += a1;
    }
    __syncthreads();

    // stream tile to gmem: 64 ch x 50 float4, coalesced
    int b  = r / (GZ * GX);
    int zx = r % (GZ * GX);
    int z = zx / GX, x = zx % GX;
    float* ob = out + ((size_t)(b * GZ + z) * CH) * XY + (size_t)x * GY;

    for (int i2 = tid; i2 < CH * (GY / 4); i2 += 256) {
        int c  = i2 / (GY / 4);
        int y4 = (i2 % (GY / 4)) * 4;
        const float* a = &acc[c * PADY + y4];
        float4 v = make_float4(a[0], a[1], a[2], a[3]);
        *reinterpret_cast<float4*>(ob + (size_t)c * XY + y4) = v;
    }
}

extern "C" void kernel_launch(void* const* d_in, const int* in_sizes, int n_in,
                              void* d_out, int out_size)
{
    const float* geo   = (const float*)d_in[0];
    const float* feat  = (const float*)d_in[1];
    const float* vsize = (const float*)d_in[2];
    const float* vorig = (const float*)d_in[3];
    float* out = (float*)d_out;

    vp_bin_fill<<<(PTOT + 255) / 256, 256>>>(geo, vsize, vorig);
    vp_rowpool<<<NROWS, 256>>>(feat, out);
}